// round 6
// baseline (speedup 1.0000x reference)
#include <cuda_runtime.h>
#include <cuda_bf16.h>
#include <cstdint>

// Problem constants
#define NB 8
#define NL 512
#define NS 64
#define NR 512        // NB*NS
#define D1 1024
#define D2 2048

typedef __nv_bfloat16 bf16;

// ---------------------------------------------------------------------------
// Device scratch
// ---------------------------------------------------------------------------
// activation splits [M][K]
__device__ bf16 g_a1sh[NR * D1], g_a1sl[NR * D1];
__device__ bf16 g_a1eh[NR * D1], g_a1el[NR * D1];
__device__ bf16 g_t1sh[NR * D2], g_t1sl[NR * D2];
__device__ bf16 g_t1eh[NR * D2], g_t1el[NR * D2];
__device__ bf16 g_cath[NR * D2], g_catl[NR * D2];
__device__ bf16 g_enth[NR * D2], g_entl[NR * D2];
__device__ float g_hi[NR * D2];   // ent@Wr1a + br1 (fp32)
__device__ float g_hj[NR * D2];   // ent@Wr1b
// weight splits [N][K]
__device__ bf16 g_ws1h[D2 * D1], g_ws1l[D2 * D1];
__device__ bf16 g_we1h[D2 * D1], g_we1l[D2 * D1];
__device__ bf16 g_ws2h[D1 * D2], g_ws2l[D1 * D2];
__device__ bf16 g_we2h[D1 * D2], g_we2l[D1 * D2];
__device__ bf16 g_woh [D2 * D2], g_wol [D2 * D2];
__device__ bf16 g_wr1ah[D2 * D2], g_wr1al[D2 * D2];
__device__ bf16 g_wr1bh[D2 * D2], g_wr1bl[D2 * D2];
__device__ bf16 g_w2h [D1 * D2], g_w2l [D1 * D2];

// ---------------------------------------------------------------------------
// PTX helpers (portable sm_80-level only)
// ---------------------------------------------------------------------------
static __device__ __forceinline__ uint32_t smem_u32(const void* p) {
    uint32_t a;
    asm("{ .reg .u64 t; cvta.to.shared.u64 t, %1; cvt.u32.u64 %0, t; }"
        : "=r"(a) : "l"(p));
    return a;
}
static __device__ __forceinline__ void cp16(uint32_t dst, const void* src) {
    asm volatile("cp.async.cg.shared.global [%0], [%1], 16;" :: "r"(dst), "l"(src));
}
#define CP_COMMIT() asm volatile("cp.async.commit_group;" ::: "memory")
#define CP_WAIT(n)  asm volatile("cp.async.wait_group %0;" :: "n"(n) : "memory")

static __device__ __forceinline__ void ldsm4(uint32_t r[4], uint32_t addr) {
    asm volatile("ldmatrix.sync.aligned.m8n8.x4.shared.b16 {%0,%1,%2,%3}, [%4];"
                 : "=r"(r[0]), "=r"(r[1]), "=r"(r[2]), "=r"(r[3]) : "r"(addr));
}
static __device__ __forceinline__ void mma16816(float c[4], const uint32_t a[4],
                                                uint32_t b0, uint32_t b1) {
    asm volatile(
        "mma.sync.aligned.m16n8k16.row.col.f32.bf16.bf16.f32 "
        "{%0,%1,%2,%3}, {%4,%5,%6,%7}, {%8,%9}, {%0,%1,%2,%3};"
        : "+f"(c[0]), "+f"(c[1]), "+f"(c[2]), "+f"(c[3])
        : "r"(a[0]), "r"(a[1]), "r"(a[2]), "r"(a[3]), "r"(b0), "r"(b1));
}
static __device__ __forceinline__ uint32_t pack2(bf16 a, bf16 b) {
    __nv_bfloat162 t = __halves2bfloat162(a, b);
    return *(uint32_t*)&t;
}

// ---------------------------------------------------------------------------
// Gather + split: h rows -> bf16 hi/lo activation splits for layer 1
// ---------------------------------------------------------------------------
__global__ void gather_split_kernel(const float* __restrict__ h,
                                    const int* __restrict__ span)
{
    int bn = blockIdx.x;
    int b  = bn >> 6;
    int si = span[2 * bn + 0];
    int ei = span[2 * bn + 1];
    const float4* ps = (const float4*)(h + ((size_t)b * NL + (size_t)si) * D1);
    const float4* pe = (const float4*)(h + ((size_t)b * NL + (size_t)ei) * D1);
    int t = threadIdx.x;                 // 256 threads, 4 elems each
    float4 vs = ps[t], ve = pe[t];
#pragma unroll
    for (int side = 0; side < 2; side++) {
        float4 v = side ? ve : vs;
        bf16 h0 = __float2bfloat16_rn(v.x), h1 = __float2bfloat16_rn(v.y);
        bf16 h2 = __float2bfloat16_rn(v.z), h3 = __float2bfloat16_rn(v.w);
        uint2 hp = make_uint2(pack2(h0, h1), pack2(h2, h3));
        uint2 lp = make_uint2(
            pack2(__float2bfloat16_rn(v.x - __bfloat162float(h0)),
                  __float2bfloat16_rn(v.y - __bfloat162float(h1))),
            pack2(__float2bfloat16_rn(v.z - __bfloat162float(h2)),
                  __float2bfloat16_rn(v.w - __bfloat162float(h3))));
        size_t o = (size_t)bn * D1 + t * 4;
        if (side == 0) {
            *(uint2*)(g_a1sh + o) = hp;
            *(uint2*)(g_a1sl + o) = lp;
        } else {
            *(uint2*)(g_a1eh + o) = hp;
            *(uint2*)(g_a1el + o) = lp;
        }
    }
}

// ---------------------------------------------------------------------------
// Generic prep: W [K][N] fp32 -> [N][K] bf16 hi/lo
// ---------------------------------------------------------------------------
__global__ void prep_split_kernel(const float* __restrict__ W,
                                  bf16* __restrict__ oh, bf16* __restrict__ ol,
                                  int K, int N)
{
    __shared__ float tile[32][33];
    int n0 = blockIdx.x * 32;
    int k0 = blockIdx.y * 32;
    int tx = threadIdx.x, ty = threadIdx.y;
    for (int i = ty; i < 32; i += 8)
        tile[i][tx] = W[(size_t)(k0 + i) * N + n0 + tx];
    __syncthreads();
    for (int i = ty; i < 32; i += 8) {
        float v = tile[tx][i];               // = W[k0+tx][n0+i]
        bf16 hv = __float2bfloat16_rn(v);
        size_t o = (size_t)(n0 + i) * K + k0 + tx;
        oh[o] = hv;
        ol[o] = __float2bfloat16_rn(v - __bfloat162float(hv));
    }
}

// ---------------------------------------------------------------------------
// Unified HMMA GEMM (3-term bf16 split, fp32 accum), dual z-batched.
//   C[M,N] = act(A[M,K] @ B^T[N,K] + bias)
// CTA 128x128 tile, KC=32, double-buffered cp.async.
// ---------------------------------------------------------------------------
#define KC   32
#define RSTR 80
#define AHO  0
#define ALO_ 10240
#define BHO  20480
#define BLO_ 30720
#define STG  40960
#define MMA_SMEM (2 * STG)   // 81920

template<bool RELU, bool SPLIT_OUT, bool F32_OUT>
__global__ __launch_bounds__(256)
void mma_gemm(const bf16* __restrict__ A0h, const bf16* __restrict__ A0l,
              const bf16* __restrict__ B0h, const bf16* __restrict__ B0l,
              const float* __restrict__ bias0,
              bf16* __restrict__ C0h, bf16* __restrict__ C0l, float* __restrict__ C0f,
              const bf16* __restrict__ A1h, const bf16* __restrict__ A1l,
              const bf16* __restrict__ B1h, const bf16* __restrict__ B1l,
              const float* __restrict__ bias1,
              bf16* __restrict__ C1h, bf16* __restrict__ C1l, float* __restrict__ C1f,
              int K, int ldc)
{
    const bf16* Ah = blockIdx.z ? A1h : A0h;
    const bf16* Al = blockIdx.z ? A1l : A0l;
    const bf16* Bh = blockIdx.z ? B1h : B0h;
    const bf16* Bl = blockIdx.z ? B1l : B0l;
    const float* bias = blockIdx.z ? bias1 : bias0;
    bf16* Ch = blockIdx.z ? C1h : C0h;
    bf16* Cl = blockIdx.z ? C1l : C0l;
    float* Cf = blockIdx.z ? C1f : C0f;

    extern __shared__ char smem[];
    const uint32_t sb = smem_u32(smem);
    const int tid  = threadIdx.x;
    const int lane = tid & 31;
    const int wid  = tid >> 5;
    const int wm   = wid >> 2;
    const int wn   = wid & 3;
    const int colBase = blockIdx.x * 128;
    const int rowBase = blockIdx.y * 128;

    const int fr = tid >> 1;             // fill row 0..127
    const int fb = (tid & 1) * 32;       // byte offset in row (0 / 32)
    const int fe = fb >> 1;              // elem offset (0 / 16)
    const bf16* gAh = Ah + (size_t)(rowBase + fr) * K + fe;
    const bf16* gAl = Al + (size_t)(rowBase + fr) * K + fe;
    const bf16* gBh = Bh + (size_t)(colBase + fr) * K + fe;
    const bf16* gBl = Bl + (size_t)(colBase + fr) * K + fe;
    const uint32_t fOff = (uint32_t)(fr * RSTR + fb);

    float acc[4][4][4];
#pragma unroll
    for (int a = 0; a < 4; a++)
#pragma unroll
        for (int b = 0; b < 4; b++)
#pragma unroll
            for (int c = 0; c < 4; c++) acc[a][b][c] = 0.f;

    auto fill = [&](int c) {
        const int st = (c & 1) * STG;
        const int k0 = c * KC;
        cp16(sb + AHO  + st + fOff, gAh + k0);
        cp16(sb + AHO  + st + fOff + 16, gAh + k0 + 8);
        cp16(sb + ALO_ + st + fOff, gAl + k0);
        cp16(sb + ALO_ + st + fOff + 16, gAl + k0 + 8);
        cp16(sb + BHO  + st + fOff, gBh + k0);
        cp16(sb + BHO  + st + fOff + 16, gBh + k0 + 8);
        cp16(sb + BLO_ + st + fOff, gBl + k0);
        cp16(sb + BLO_ + st + fOff + 16, gBl + k0 + 8);
    };

    const uint32_t aOff = (uint32_t)((wm * 64 + (lane & 15)) * RSTR + ((lane >> 4) * 8) * 2);
    const uint32_t bOff = (uint32_t)((wn * 32 + (lane & 7) + ((lane >> 4) & 1) * 8) * RSTR
                                     + (((lane >> 3) & 1) * 8) * 2);

    const int NCK = K / KC;
    fill(0);
    CP_COMMIT();

    for (int c = 0; c < NCK; c++) {
        if (c + 1 < NCK) { fill(c + 1); CP_COMMIT(); CP_WAIT(1); }
        else             { CP_WAIT(0); }
        __syncthreads();

        const int st = (c & 1) * STG;
        const uint32_t aH = sb + AHO + st + aOff;
        const uint32_t aL = sb + ALO_ + st + aOff;
        const uint32_t bH = sb + BHO + st + bOff;
        const uint32_t bL = sb + BLO_ + st + bOff;

#pragma unroll
        for (int ks = 0; ks < KC; ks += 16) {
            uint32_t ah[4][4], al4[4][4], bh[2][4], bl[2][4];
#pragma unroll
            for (int mt = 0; mt < 4; mt++) {
                ldsm4(ah[mt],  aH + mt * (16 * RSTR) + ks * 2);
                ldsm4(al4[mt], aL + mt * (16 * RSTR) + ks * 2);
            }
#pragma unroll
            for (int np = 0; np < 2; np++) {
                ldsm4(bh[np], bH + np * (16 * RSTR) + ks * 2);
                ldsm4(bl[np], bL + np * (16 * RSTR) + ks * 2);
            }
#pragma unroll
            for (int mt = 0; mt < 4; mt++) {
#pragma unroll
                for (int nt = 0; nt < 4; nt++) {
                    const int np = nt >> 1, h = (nt & 1) * 2;
                    mma16816(acc[mt][nt], ah[mt],  bh[np][h], bh[np][h + 1]);
                    mma16816(acc[mt][nt], ah[mt],  bl[np][h], bl[np][h + 1]);
                    mma16816(acc[mt][nt], al4[mt], bh[np][h], bh[np][h + 1]);
                }
            }
        }
        __syncthreads();
    }

    // ---- epilogue ----
#pragma unroll
    for (int mt = 0; mt < 4; mt++) {
        const int r0 = rowBase + wm * 64 + mt * 16 + (lane >> 2);
#pragma unroll
        for (int nt = 0; nt < 4; nt++) {
            const int col = colBase + wn * 32 + nt * 8 + (lane & 3) * 2;
            float b0 = 0.f, b1 = 0.f;
            if (bias) { b0 = bias[col]; b1 = bias[col + 1]; }
#pragma unroll
            for (int rr = 0; rr < 2; rr++) {
                const int r = r0 + rr * 8;
                float v0 = acc[mt][nt][2 * rr + 0] + b0;
                float v1 = acc[mt][nt][2 * rr + 1] + b1;
                if (RELU) { v0 = fmaxf(v0, 0.f); v1 = fmaxf(v1, 0.f); }
                const size_t o = (size_t)r * ldc + col;
                if (F32_OUT)
                    *(float2*)(Cf + o) = make_float2(v0, v1);
                if (SPLIT_OUT) {
                    bf16 h0 = __float2bfloat16_rn(v0);
                    bf16 h1 = __float2bfloat16_rn(v1);
                    *(uint32_t*)(Ch + o) = pack2(h0, h1);
                    *(uint32_t*)(Cl + o) =
                        pack2(__float2bfloat16_rn(v0 - __bfloat162float(h0)),
                              __float2bfloat16_rn(v1 - __bfloat162float(h1)));
                }
            }
        }
    }
}

// ---------------------------------------------------------------------------
// Final GEMM on HMMA (unchanged from validated R5 version)
//   out[m,n] = relu(hi'[b,i,:] + hj[b,j,:]) @ Wr2 + br2
// ---------------------------------------------------------------------------
__global__ __launch_bounds__(256)
void final_mma_kernel(const float* __restrict__ br2, float* __restrict__ out)
{
    extern __shared__ char smem[];
    const uint32_t sb = smem_u32(smem);
    const int tid  = threadIdx.x;
    const int lane = tid & 31;
    const int wid  = tid >> 5;
    const int wm   = wid >> 2;
    const int wn   = wid & 3;
    const int colBase = blockIdx.x * 128;
    const int rowBase = blockIdx.y * 128;

    const int fr = tid >> 1;
    const int fk = (tid & 1) << 4;
    const int m  = rowBase + fr;
    const int bI = m >> 12, iI = (m >> 6) & 63, jI = m & 63;
    const float* hiRow = g_hi + (size_t)((bI << 6) + iI) * D2;
    const float* hjRow = g_hj + (size_t)((bI << 6) + jI) * D2;
    const bf16* bhRow = g_w2h + (size_t)(colBase + fr) * D2;
    const bf16* blRow = g_w2l + (size_t)(colBase + fr) * D2;
    const uint32_t fillOff = (uint32_t)(fr * RSTR + fk * 2);

    float acc[4][4][4];
#pragma unroll
    for (int a = 0; a < 4; a++)
#pragma unroll
        for (int b = 0; b < 4; b++)
#pragma unroll
            for (int c = 0; c < 4; c++) acc[a][b][c] = 0.f;

    auto fill_stage = [&](int c) {
        const int st = (c & 1) * STG;
        const int k0 = c * KC;
        {
            uint32_t d = sb + BHO + st + fillOff;
            cp16(d,      bhRow + k0 + fk);
            cp16(d + 16, bhRow + k0 + fk + 8);
            d = sb + BLO_ + st + fillOff;
            cp16(d,      blRow + k0 + fk);
            cp16(d + 16, blRow + k0 + fk + 8);
        }
        const float4* xp = (const float4*)(hiRow + k0 + fk);
        const float4* yp = (const float4*)(hjRow + k0 + fk);
        uint32_t ah[8], al[8];
#pragma unroll
        for (int q = 0; q < 4; q++) {
            float4 x = xp[q], y = yp[q];
            float v0 = fmaxf(x.x + y.x, 0.f);
            float v1 = fmaxf(x.y + y.y, 0.f);
            float v2 = fmaxf(x.z + y.z, 0.f);
            float v3 = fmaxf(x.w + y.w, 0.f);
            bf16 h0 = __float2bfloat16_rn(v0);
            bf16 h1 = __float2bfloat16_rn(v1);
            bf16 h2 = __float2bfloat16_rn(v2);
            bf16 h3 = __float2bfloat16_rn(v3);
            ah[2 * q + 0] = pack2(h0, h1);
            ah[2 * q + 1] = pack2(h2, h3);
            al[2 * q + 0] = pack2(__float2bfloat16_rn(v0 - __bfloat162float(h0)),
                                  __float2bfloat16_rn(v1 - __bfloat162float(h1)));
            al[2 * q + 1] = pack2(__float2bfloat16_rn(v2 - __bfloat162float(h2)),
                                  __float2bfloat16_rn(v3 - __bfloat162float(h3)));
        }
        char* da = smem + AHO + st + fillOff;
        *(uint4*)(da)      = make_uint4(ah[0], ah[1], ah[2], ah[3]);
        *(uint4*)(da + 16) = make_uint4(ah[4], ah[5], ah[6], ah[7]);
        char* dl = smem + ALO_ + st + fillOff;
        *(uint4*)(dl)      = make_uint4(al[0], al[1], al[2], al[3]);
        *(uint4*)(dl + 16) = make_uint4(al[4], al[5], al[6], al[7]);
    };

    const uint32_t aOff = (uint32_t)((wm * 64 + (lane & 15)) * RSTR + ((lane >> 4) * 8) * 2);
    const uint32_t bOff = (uint32_t)((wn * 32 + (lane & 7) + ((lane >> 4) & 1) * 8) * RSTR
                                     + (((lane >> 3) & 1) * 8) * 2);

    fill_stage(0);
    CP_COMMIT();

    const int NCK = D2 / KC;
    for (int c = 0; c < NCK; c++) {
        if (c + 1 < NCK) { fill_stage(c + 1); CP_COMMIT(); CP_WAIT(1); }
        else             { CP_WAIT(0); }
        __syncthreads();

        const int st = (c & 1) * STG;
        const uint32_t aH = sb + AHO + st + aOff;
        const uint32_t aL = sb + ALO_ + st + aOff;
        const uint32_t bH = sb + BHO + st + bOff;
        const uint32_t bL = sb + BLO_ + st + bOff;

#pragma unroll
        for (int ks = 0; ks < KC; ks += 16) {
            uint32_t ah[4][4], al4[4][4], bh[2][4], bl[2][4];
#pragma unroll
            for (int mt = 0; mt < 4; mt++) {
                ldsm4(ah[mt],  aH + mt * (16 * RSTR) + ks * 2);
                ldsm4(al4[mt], aL + mt * (16 * RSTR) + ks * 2);
            }
#pragma unroll
            for (int np = 0; np < 2; np++) {
                ldsm4(bh[np], bH + np * (16 * RSTR) + ks * 2);
                ldsm4(bl[np], bL + np * (16 * RSTR) + ks * 2);
            }
#pragma unroll
            for (int mt = 0; mt < 4; mt++) {
#pragma unroll
                for (int nt = 0; nt < 4; nt++) {
                    const int np = nt >> 1, h = (nt & 1) * 2;
                    mma16816(acc[mt][nt], ah[mt],  bh[np][h], bh[np][h + 1]);
                    mma16816(acc[mt][nt], ah[mt],  bl[np][h], bl[np][h + 1]);
                    mma16816(acc[mt][nt], al4[mt], bh[np][h], bh[np][h + 1]);
                }
            }
        }
        __syncthreads();
    }

#pragma unroll
    for (int mt = 0; mt < 4; mt++) {
        const int r0 = rowBase + wm * 64 + mt * 16 + (lane >> 2);
#pragma unroll
        for (int nt = 0; nt < 4; nt++) {
            const int col = colBase + wn * 32 + nt * 8 + (lane & 3) * 2;
            const float b0 = br2[col], b1 = br2[col + 1];
            float2 v01 = make_float2(acc[mt][nt][0] + b0, acc[mt][nt][1] + b1);
            float2 v23 = make_float2(acc[mt][nt][2] + b0, acc[mt][nt][3] + b1);
            *(float2*)(out + (size_t)r0 * D1 + col)       = v01;
            *(float2*)(out + (size_t)(r0 + 8) * D1 + col) = v23;
        }
    }
}

// ---------------------------------------------------------------------------
// Launcher
// ---------------------------------------------------------------------------
extern "C" void kernel_launch(void* const* d_in, const int* in_sizes, int n_in,
                              void* d_out, int out_size)
{
    const float* h    = (const float*)d_in[0];
    const int*   span = (const int*)d_in[1];
    const float* Ws1 = (const float*)d_in[2];
    const float* bs1 = (const float*)d_in[3];
    const float* Ws2 = (const float*)d_in[4];
    const float* bs2 = (const float*)d_in[5];
    const float* We1 = (const float*)d_in[6];
    const float* be1 = (const float*)d_in[7];
    const float* We2 = (const float*)d_in[8];
    const float* be2 = (const float*)d_in[9];
    const float* Wo  = (const float*)d_in[10];
    const float* bo  = (const float*)d_in[11];
    const float* Wr1 = (const float*)d_in[12];
    const float* br1 = (const float*)d_in[13];
    const float* Wr2 = (const float*)d_in[14];
    const float* br2 = (const float*)d_in[15];
    float* out = (float*)d_out;

    // symbol addresses
    bf16 *a1sh, *a1sl, *a1eh, *a1el, *t1sh, *t1sl, *t1eh, *t1el;
    bf16 *cath, *catl, *enth, *entl;
    bf16 *ws1h, *ws1l, *we1h, *we1l, *ws2h, *ws2l, *we2h, *we2l;
    bf16 *woh, *wol, *wr1ah, *wr1al, *wr1bh, *wr1bl, *w2h, *w2l;
    float *hi, *hj;
    cudaGetSymbolAddress((void**)&a1sh, g_a1sh); cudaGetSymbolAddress((void**)&a1sl, g_a1sl);
    cudaGetSymbolAddress((void**)&a1eh, g_a1eh); cudaGetSymbolAddress((void**)&a1el, g_a1el);
    cudaGetSymbolAddress((void**)&t1sh, g_t1sh); cudaGetSymbolAddress((void**)&t1sl, g_t1sl);
    cudaGetSymbolAddress((void**)&t1eh, g_t1eh); cudaGetSymbolAddress((void**)&t1el, g_t1el);
    cudaGetSymbolAddress((void**)&cath, g_cath); cudaGetSymbolAddress((void**)&catl, g_catl);
    cudaGetSymbolAddress((void**)&enth, g_enth); cudaGetSymbolAddress((void**)&entl, g_entl);
    cudaGetSymbolAddress((void**)&ws1h, g_ws1h); cudaGetSymbolAddress((void**)&ws1l, g_ws1l);
    cudaGetSymbolAddress((void**)&we1h, g_we1h); cudaGetSymbolAddress((void**)&we1l, g_we1l);
    cudaGetSymbolAddress((void**)&ws2h, g_ws2h); cudaGetSymbolAddress((void**)&ws2l, g_ws2l);
    cudaGetSymbolAddress((void**)&we2h, g_we2h); cudaGetSymbolAddress((void**)&we2l, g_we2l);
    cudaGetSymbolAddress((void**)&woh,  g_woh);  cudaGetSymbolAddress((void**)&wol,  g_wol);
    cudaGetSymbolAddress((void**)&wr1ah, g_wr1ah); cudaGetSymbolAddress((void**)&wr1al, g_wr1al);
    cudaGetSymbolAddress((void**)&wr1bh, g_wr1bh); cudaGetSymbolAddress((void**)&wr1bl, g_wr1bl);
    cudaGetSymbolAddress((void**)&w2h,  g_w2h);  cudaGetSymbolAddress((void**)&w2l,  g_w2l);
    cudaGetSymbolAddress((void**)&hi,   g_hi);   cudaGetSymbolAddress((void**)&hj,   g_hj);

    cudaFuncSetAttribute(final_mma_kernel,
                         cudaFuncAttributeMaxDynamicSharedMemorySize, MMA_SMEM);
    cudaFuncSetAttribute(mma_gemm<true,  true,  false>,
                         cudaFuncAttributeMaxDynamicSharedMemorySize, MMA_SMEM);
    cudaFuncSetAttribute(mma_gemm<false, true,  false>,
                         cudaFuncAttributeMaxDynamicSharedMemorySize, MMA_SMEM);
    cudaFuncSetAttribute(mma_gemm<false, false, true>,
                         cudaFuncAttributeMaxDynamicSharedMemorySize, MMA_SMEM);

    const dim3 tb(32, 8);

    // 0) weight prep (transpose + bf16 split); independent of data path
    prep_split_kernel<<<dim3(D2 / 32, D1 / 32), tb>>>(Ws1, ws1h, ws1l, D1, D2);
    prep_split_kernel<<<dim3(D2 / 32, D1 / 32), tb>>>(We1, we1h, we1l, D1, D2);
    prep_split_kernel<<<dim3(D1 / 32, D2 / 32), tb>>>(Ws2, ws2h, ws2l, D2, D1);
    prep_split_kernel<<<dim3(D1 / 32, D2 / 32), tb>>>(We2, we2h, we2l, D2, D1);
    prep_split_kernel<<<dim3(D2 / 32, D2 / 32), tb>>>(Wo,  woh,  wol,  D2, D2);
    prep_split_kernel<<<dim3(D2 / 32, D2 / 32), tb>>>(Wr1,                    wr1ah, wr1al, D2, D2);
    prep_split_kernel<<<dim3(D2 / 32, D2 / 32), tb>>>(Wr1 + (size_t)D2 * D2,  wr1bh, wr1bl, D2, D2);
    prep_split_kernel<<<dim3(D1 / 32, D2 / 32), tb>>>(Wr2, w2h, w2l, D2, D1);

    // 1) gather + split span rows
    gather_split_kernel<<<NR, 256>>>(h, span);

    // 2) layer 1 (s & e): (512,1024)@(1024,2048), relu, split out
    mma_gemm<true, true, false><<<dim3(D2 / 128, NR / 128, 2), 256, MMA_SMEM>>>(
        a1sh, a1sl, ws1h, ws1l, bs1, t1sh, t1sl, nullptr,
        a1eh, a1el, we1h, we1l, be1, t1eh, t1el, nullptr, D1, D2);

    // 3) layer 2 (s & e) + concat relu: (512,2048)@(2048,1024) -> cat halves
    mma_gemm<true, true, false><<<dim3(D1 / 128, NR / 128, 2), 256, MMA_SMEM>>>(
        t1sh, t1sl, ws2h, ws2l, bs2, cath,      catl,      nullptr,
        t1eh, t1el, we2h, we2l, be2, cath + D1, catl + D1, nullptr, D2, D2);

    // 4) entity_reps = cat @ Wo + bo: (512,2048)@(2048,2048), split out
    mma_gemm<false, true, false><<<dim3(D2 / 128, NR / 128, 1), 256, MMA_SMEM>>>(
        cath, catl, woh, wol, bo, enth, entl, nullptr,
        cath, catl, woh, wol, bo, enth, entl, nullptr, D2, D2);

    // 5) hi = ent@Wr1a + br1 (folded), hj = ent@Wr1b; fp32 out
    mma_gemm<false, false, true><<<dim3(D2 / 128, NR / 128, 2), 256, MMA_SMEM>>>(
        enth, entl, wr1ah, wr1al, br1,     nullptr, nullptr, hi,
        enth, entl, wr1bh, wr1bl, nullptr, nullptr, nullptr, hj, D2, D2);

    // 6) final fused GEMM (HMMA): M=32768, N=1024, K=2048
    final_mma_kernel<<<dim3(D1 / 128, (NB * NS * NS) / 128), 256, MMA_SMEM>>>(
        br2, out);
}